// round 14
// baseline (speedup 1.0000x reference)
#include <cuda_runtime.h>
#include <cuda_bf16.h>
#include <cstdint>

// RVQ via mma.sync bf16 (6-term error-free split ~ fp32 parity):
// s[tok][k] = mel @ E^T (E = [cb0;cb1] @ w_in, 256x128), argmin w/ Gram fold,
// decode via tables. 64-token tiles, B staged in nf-halves -> 2 CTAs/SM.

#define NTOK   (32 * 4096)
#define TILE_T 64
#define NTILE  (NTOK / TILE_T)   // 2048
#define NTHR   256

// ---- precomputed tables ----
__device__ __align__(16) float g_twoG[128 * 128]; // 2 * cb0[j] . cb1[k]
__device__ __align__(16) float g_dec0[128 * 128]; // cb0[j] @ w_out^T + b_out
__device__ __align__(16) float g_dec1[128 * 128]; // cb1[j] @ w_out^T
__device__ __align__(16) float g_adj0[128];       // ||c0||^2 - 2 b.c0
__device__ __align__(16) float g_adj1[128];       // ||c1||^2 - 2 b.c1
// B fragment images, mma.m16n8k16 layout, 3 bf16 splits:
// idx = ((pass*8 + kst)*16 + nf)*32 + lane
// g_B12[idx] = uint4{ b0_s1, b1_s1, b0_s2, b1_s2 };  g_B3[idx] = uint2{ b0_s3, b1_s3 }
__device__ __align__(16) uint32_t g_B12[2 * 8 * 16 * 32 * 4]; // 128KB
__device__ __align__(16) uint32_t g_B3 [2 * 8 * 16 * 32 * 2]; // 64KB

__device__ __forceinline__ float dot64(const float* __restrict__ a,
                                       const float* __restrict__ b) {
    float s = 0.f;
    const float4* b4 = (const float4*)b;
#pragma unroll
    for (int q = 0; q < 16; ++q) {
        float4 v = b4[q];
        s += a[4*q+0]*v.x + a[4*q+1]*v.y + a[4*q+2]*v.z + a[4*q+3]*v.w;
    }
    return s;
}

// write one E value (3 bf16 splits) into the packed fragment images
__device__ __forceinline__ void write_B(int pass, int n, int k, float v) {
    const int nf = n >> 3, lg = n & 7;
    const int kst = k >> 4, kk = k & 15;
    const int kh = kk >> 3;          // b0 vs b1 reg
    const int lc = (kk & 7) >> 1;    // lane&3
    const int hl = kk & 1;           // lo/hi bf16 in reg
    const int lane = lg * 4 + lc;
    const int idx = ((pass * 8 + kst) * 16 + nf) * 32 + lane;
    unsigned short* B12 = (unsigned short*)g_B12;
    unsigned short* B3  = (unsigned short*)g_B3;
#pragma unroll
    for (int s = 0; s < 3; ++s) {
        __nv_bfloat16 h = __float2bfloat16_rn(v);
        unsigned short us = __bfloat16_as_ushort(h);
        if (s < 2) B12[(idx * 4 + 2 * s + kh) * 2 + hl] = us;
        else       B3 [(idx * 2 + kh) * 2 + hl] = us;
        v -= __bfloat162float(h);
    }
}

__global__ void rvq_precompute(const float* __restrict__ w_in,
                               const float* __restrict__ b_in,
                               const float* __restrict__ cb0,
                               const float* __restrict__ cb1,
                               const float* __restrict__ w_out,
                               const float* __restrict__ b_out) {
    __shared__ float c0r[64], c1r[64];
    const int j = blockIdx.x;      // 0..127
    const int t = threadIdx.x;     // 0..255
    if (t < 64)        c0r[t]      = cb0[j * 64 + t];
    else if (t < 128)  c1r[t - 64] = cb1[j * 64 + (t - 64)];
    __syncthreads();

    if (t < 128) {
        g_twoG[j * 128 + t] = 2.f * dot64(c0r, cb1 + t * 64);
        g_dec1[j * 128 + t] = dot64(c1r, w_out + t * 64);
        const int m = t;
        float e0 = 0.f, e1 = 0.f;
#pragma unroll 8
        for (int d = 0; d < 64; ++d) {
            float w = w_in[d * 128 + m];
            e0 += c0r[d] * w; e1 += c1r[d] * w;
        }
        write_B(0, j, m, e0);     // pass 0: cb0 codes
        write_B(1, j, m, e1);     // pass 1: cb1 codes
    } else {
        int m = t - 128;
        g_dec0[j * 128 + m] = dot64(c0r, w_out + m * 64) + b_out[m];
    }
    if (t == 0) {
        float n = 0.f, db = 0.f;
        for (int d = 0; d < 64; ++d) { n += c0r[d]*c0r[d]; db += b_in[d]*c0r[d]; }
        g_adj0[j] = n - 2.f * db;
    }
    if (t == 32) {
        float n = 0.f, db = 0.f;
        for (int d = 0; d < 64; ++d) { n += c1r[d]*c1r[d]; db += b_in[d]*c1r[d]; }
        g_adj1[j] = n - 2.f * db;
    }
}

__device__ __forceinline__ void mma_bf16(float* d, const uint32_t* a,
                                         uint32_t b0, uint32_t b1) {
    asm volatile(
        "mma.sync.aligned.m16n8k16.row.col.f32.bf16.bf16.f32 "
        "{%0,%1,%2,%3}, {%4,%5,%6,%7}, {%8,%9}, {%0,%1,%2,%3};\n"
        : "+f"(d[0]), "+f"(d[1]), "+f"(d[2]), "+f"(d[3])
        : "r"(a[0]), "r"(a[1]), "r"(a[2]), "r"(a[3]), "r"(b0), "r"(b1));
}

// smem bytes:
//  A fp32 [64][132]          0 .. 33792
//  B12 half [8][8][32] uint4 33792 .. 66560
//  B3  half [8][8][32] uint2 66560 .. 82944
//  pv [64][17] f32           82944 .. 87296
//  pk [64][17] i32           87296 .. 91648
//  bv [64]                   91648 .. 91904
//  bk [64]                   91904 .. 92160
//  i0s[64]                   92160 .. 92416
//  i1s[64]                   92416 .. 92672
#define OFF_B12 33792
#define OFF_B3  66560
#define OFF_PV  82944
#define OFF_PK  87296
#define OFF_BV  91648
#define OFF_BK  91904
#define OFF_I0  92160
#define OFF_I1  92416
#define SMEM_BYTES 92672

__global__ void __launch_bounds__(NTHR, 2)
rvq_main(const float* __restrict__ mel, float* __restrict__ out) {
    extern __shared__ __align__(16) uint8_t smem[];
    float* smA   = (float*)smem;                    // [64][132]
    uint4* smB12 = (uint4*)(smem + OFF_B12);        // [8][8][32]
    uint2* smB3  = (uint2*)(smem + OFF_B3);         // [8][8][32]
    float* pv    = (float*)(smem + OFF_PV);         // [64][17]
    int*   pk    = (int*)(smem + OFF_PK);           // [64][17]
    float* bv    = (float*)(smem + OFF_BV);
    int*   bk    = (int*)(smem + OFF_BK);
    int*   i0s   = (int*)(smem + OFF_I0);
    int*   i1s   = (int*)(smem + OFF_I1);

    const int tid  = threadIdx.x;
    const int lane = tid & 31;
    const int wid  = tid >> 5;
    const int tile = blockIdx.x;
    const int g    = lane >> 2;    // mma group id (row)
    const int tt   = lane & 3;     // thread-in-group (col pair)
    const int mw   = wid & 1;      // token half of tile
    const int nw   = wid >> 1;     // code quarter within half (16 codes)
    const int tokB = mw * 32;

    // ---- stage mel (64 tok x 128, pad 132) ----
    {
        const float4* mg = (const float4*)mel + (size_t)tile * 2048;
#pragma unroll
        for (int r = 0; r < 8; ++r) {
            int f = tid + NTHR * r;            // 0..2047 float4
            int tok = f >> 5, m4 = f & 31;
            *(float4*)(smA + tok * 132 + m4 * 4) = mg[f];
        }
    }

#pragma unroll 1
    for (int ch = 0; ch < 2; ++ch) {
#pragma unroll 1
        for (int h = 0; h < 2; ++h) {
            __syncthreads();   // A staged / prior pv-pk & B reads done
            // ---- stage B half: nf in [h*8, h*8+8) ----
            {
                const uint4* gb12 = (const uint4*)g_B12;
#pragma unroll
                for (int r = 0; r < 8; ++r) {
                    int f = tid + NTHR * r;            // 0..2047
                    int kst = f >> 8, inner = f & 255;
                    smB12[f] = gb12[(ch * 8 + kst) * 512 + (h * 8) * 32 + inner];
                }
                const uint4* gb3 = (const uint4*)g_B3;
                uint4* sb3 = (uint4*)smB3;
#pragma unroll
                for (int r = 0; r < 4; ++r) {
                    int f = tid + NTHR * r;            // 0..1023
                    int kst = f >> 7, w = f & 127;
                    sb3[f] = gb3[((ch * 8 + kst) * 16 + h * 8) * 16 + w];
                }
            }
            __syncthreads();

            // ---- GEMM: warp = 32 tok x 16 codes, K=128, 6 split terms ----
            float d[2][2][4];
#pragma unroll
            for (int mf = 0; mf < 2; ++mf)
#pragma unroll
                for (int nfl = 0; nfl < 2; ++nfl)
#pragma unroll
                    for (int q = 0; q < 4; ++q) d[mf][nfl][q] = 0.f;

#pragma unroll 1
            for (int kst = 0; kst < 8; ++kst) {
                uint32_t A[2][3][4];
#pragma unroll
                for (int mf = 0; mf < 2; ++mf) {
                    const int r0 = tokB + mf * 16 + g;
                    const int c0 = kst * 16 + tt * 2;
                    float2 e[4];
                    e[0] = *(const float2*)(smA + r0 * 132 + c0);
                    e[1] = *(const float2*)(smA + (r0 + 8) * 132 + c0);
                    e[2] = *(const float2*)(smA + r0 * 132 + c0 + 8);
                    e[3] = *(const float2*)(smA + (r0 + 8) * 132 + c0 + 8);
#pragma unroll
                    for (int p = 0; p < 4; ++p) {
                        float lo = e[p].x, hi = e[p].y;
#pragma unroll
                        for (int s = 0; s < 3; ++s) {
                            __nv_bfloat16 bl = __float2bfloat16_rn(lo);
                            __nv_bfloat16 bh = __float2bfloat16_rn(hi);
                            A[mf][s][p] = (uint32_t)__bfloat16_as_ushort(bl)
                                        | ((uint32_t)__bfloat16_as_ushort(bh) << 16);
                            lo -= __bfloat162float(bl);
                            hi -= __bfloat162float(bh);
                        }
                    }
                }
#pragma unroll
                for (int nfl = 0; nfl < 2; ++nfl) {
                    const int bidx = (kst * 8 + nw * 2 + nfl) * 32 + lane;
                    uint4 b12 = smB12[bidx];
                    uint2 b3  = smB3[bidx];
#pragma unroll
                    for (int mf = 0; mf < 2; ++mf) {
                        mma_bf16(d[mf][nfl], A[mf][0], b12.x, b12.y);  // a1*b1
                        mma_bf16(d[mf][nfl], A[mf][0], b12.z, b12.w);  // a1*b2
                        mma_bf16(d[mf][nfl], A[mf][1], b12.x, b12.y);  // a2*b1
                        mma_bf16(d[mf][nfl], A[mf][1], b12.z, b12.w);  // a2*b2
                        mma_bf16(d[mf][nfl], A[mf][0], b3.x,  b3.y);   // a1*b3
                        mma_bf16(d[mf][nfl], A[mf][2], b12.x, b12.y);  // a3*b1
                    }
                }
            }

            // ---- fold adj (+Gram) and local argmin; write candidates ----
#pragma unroll
            for (int mf = 0; mf < 2; ++mf) {
#pragma unroll
                for (int rh = 0; rh < 2; ++rh) {
                    const int tok = tokB + mf * 16 + rh * 8 + g;
                    const int k0 = h * 64 + nw * 16 + tt * 2;   // nfl=0 pair
                    float s0 = d[mf][0][rh * 2], s1 = d[mf][0][rh * 2 + 1];
                    float s2 = d[mf][1][rh * 2], s3 = d[mf][1][rh * 2 + 1];
                    float v0, v1, v2, v3;
                    if (ch == 0) {
                        float2 a01 = *(const float2*)(g_adj0 + k0);
                        float2 a23 = *(const float2*)(g_adj0 + k0 + 8);
                        v0 = a01.x - 2.f * s0; v1 = a01.y - 2.f * s1;
                        v2 = a23.x - 2.f * s2; v3 = a23.y - 2.f * s3;
                    } else {
                        const float* grow = g_twoG + i0s[tok] * 128;
                        float2 a01 = *(const float2*)(g_adj1 + k0);
                        float2 a23 = *(const float2*)(g_adj1 + k0 + 8);
                        float2 g01 = *(const float2*)(grow + k0);
                        float2 g23 = *(const float2*)(grow + k0 + 8);
                        v0 = a01.x - 2.f * s0 + g01.x; v1 = a01.y - 2.f * s1 + g01.y;
                        v2 = a23.x - 2.f * s2 + g23.x; v3 = a23.y - 2.f * s3 + g23.y;
                    }
                    float best = v0; int bi = k0;
                    if (v1 < best) { best = v1; bi = k0 + 1; }
                    if (v2 < best) { best = v2; bi = k0 + 8; }
                    if (v3 < best) { best = v3; bi = k0 + 9; }
                    pv[tok * 17 + nw * 4 + tt] = best;
                    pk[tok * 17 + nw * 4 + tt] = bi;
                }
            }
            __syncthreads();

            // ---- reduce 16 slots per token, merge across halves ----
            if (tid < 64) {
                float best = pv[tid * 17]; int bi = pk[tid * 17];
#pragma unroll
                for (int l = 1; l < 16; ++l) {
                    float v = pv[tid * 17 + l]; int kk = pk[tid * 17 + l];
                    if (v < best || (v == best && kk < bi)) { best = v; bi = kk; }
                }
                if (h == 0) { bv[tid] = best; bk[tid] = bi; }
                else {
                    float b0 = bv[tid]; int kb = bk[tid];
                    if (best < b0 || (best == b0 && bi < kb)) { b0 = best; kb = bi; }
                    if (ch == 0) i0s[tid] = kb; else i1s[tid] = kb;
                }
            }
        }
    }
    __syncthreads();

    // ---- decode: out = dec0[i0] + dec1[i1] (coalesced float4) ----
    {
        const float4* d0 = (const float4*)g_dec0;
        const float4* d1 = (const float4*)g_dec1;
        float4* o4 = (float4*)out + (size_t)tile * 2048;
#pragma unroll
        for (int r = 0; r < 8; ++r) {
            int f = tid + NTHR * r;            // 0..2047
            int tok = f >> 5, m4 = f & 31;
            float4 va = d0[i0s[tok] * 32 + m4];
            float4 vb = d1[i1s[tok] * 32 + m4];
            o4[f] = make_float4(va.x + vb.x, va.y + vb.y, va.z + vb.z, va.w + vb.w);
        }
    }
}

extern "C" void kernel_launch(void* const* d_in, const int* in_sizes, int n_in,
                              void* d_out, int out_size) {
    const float* mel   = (const float*)d_in[0];
    const float* w_in  = (const float*)d_in[1];
    const float* b_in  = (const float*)d_in[2];
    const float* cb0   = (const float*)d_in[3];
    const float* cb1   = (const float*)d_in[4];
    const float* w_out = (const float*)d_in[5];
    const float* b_out = (const float*)d_in[6];
    float* out = (float*)d_out;

    cudaFuncSetAttribute(rvq_main, cudaFuncAttributeMaxDynamicSharedMemorySize, SMEM_BYTES);

    rvq_precompute<<<128, NTHR>>>(w_in, b_in, cb0, cb1, w_out, b_out);
    rvq_main<<<NTILE, NTHR, SMEM_BYTES>>>(mel, out);
}

// round 15
// speedup vs baseline: 1.3789x; 1.3789x over previous
#include <cuda_runtime.h>
#include <cuda_bf16.h>
#include <cstdint>

// RVQ via mma.sync bf16 (6-term error-free split ~ fp32 parity):
// s[tok][k] = mel @ E^T (E = [cb0;cb1] @ w_in, 256x128), argmin w/ Gram fold,
// decode via tables. A staged as 3 bf16-split images (ldmatrix), B staged in
// nf-halves as fragment images -> 2 CTAs/SM.

#define NTOK   (32 * 4096)
#define TILE_T 64
#define NTILE  (NTOK / TILE_T)   // 2048
#define NTHR   256

// ---- precomputed tables ----
__device__ __align__(16) float g_twoG[128 * 128]; // 2 * cb0[j] . cb1[k]
__device__ __align__(16) float g_dec0[128 * 128]; // cb0[j] @ w_out^T + b_out
__device__ __align__(16) float g_dec1[128 * 128]; // cb1[j] @ w_out^T
__device__ __align__(16) float g_adj0[128];       // ||c0||^2 - 2 b.c0
__device__ __align__(16) float g_adj1[128];       // ||c1||^2 - 2 b.c1
// B fragment images, mma.m16n8k16 layout, 3 bf16 splits:
// idx = ((pass*8 + kst)*16 + nf)*32 + lane
// g_B12[idx] = uint4{ b0_s1, b1_s1, b0_s2, b1_s2 };  g_B3[idx] = uint2{ b0_s3, b1_s3 }
__device__ __align__(16) uint32_t g_B12[2 * 8 * 16 * 32 * 4]; // 128KB
__device__ __align__(16) uint32_t g_B3 [2 * 8 * 16 * 32 * 2]; // 64KB

__device__ __forceinline__ float dot64(const float* __restrict__ a,
                                       const float* __restrict__ b) {
    float s = 0.f;
    const float4* b4 = (const float4*)b;
#pragma unroll
    for (int q = 0; q < 16; ++q) {
        float4 v = b4[q];
        s += a[4*q+0]*v.x + a[4*q+1]*v.y + a[4*q+2]*v.z + a[4*q+3]*v.w;
    }
    return s;
}

// write one E value (3 bf16 splits) into the packed fragment images
__device__ __forceinline__ void write_B(int pass, int n, int k, float v) {
    const int nf = n >> 3, lg = n & 7;
    const int kst = k >> 4, kk = k & 15;
    const int kh = kk >> 3;          // b0 vs b1 reg
    const int lc = (kk & 7) >> 1;    // lane&3
    const int hl = kk & 1;           // lo/hi bf16 in reg
    const int lane = lg * 4 + lc;
    const int idx = ((pass * 8 + kst) * 16 + nf) * 32 + lane;
    unsigned short* B12 = (unsigned short*)g_B12;
    unsigned short* B3  = (unsigned short*)g_B3;
#pragma unroll
    for (int s = 0; s < 3; ++s) {
        __nv_bfloat16 h = __float2bfloat16_rn(v);
        unsigned short us = __bfloat16_as_ushort(h);
        if (s < 2) B12[(idx * 4 + 2 * s + kh) * 2 + hl] = us;
        else       B3 [(idx * 2 + kh) * 2 + hl] = us;
        v -= __bfloat162float(h);
    }
}

__global__ void rvq_precompute(const float* __restrict__ w_in,
                               const float* __restrict__ b_in,
                               const float* __restrict__ cb0,
                               const float* __restrict__ cb1,
                               const float* __restrict__ w_out,
                               const float* __restrict__ b_out) {
    __shared__ float c0r[64], c1r[64];
    const int j = blockIdx.x;      // 0..127
    const int t = threadIdx.x;     // 0..255
    if (t < 64)        c0r[t]      = cb0[j * 64 + t];
    else if (t < 128)  c1r[t - 64] = cb1[j * 64 + (t - 64)];
    __syncthreads();

    if (t < 128) {
        g_twoG[j * 128 + t] = 2.f * dot64(c0r, cb1 + t * 64);
        g_dec1[j * 128 + t] = dot64(c1r, w_out + t * 64);
        const int m = t;
        float e0 = 0.f, e1 = 0.f;
#pragma unroll 8
        for (int d = 0; d < 64; ++d) {
            float w = w_in[d * 128 + m];
            e0 += c0r[d] * w; e1 += c1r[d] * w;
        }
        write_B(0, j, m, e0);     // pass 0: cb0 codes
        write_B(1, j, m, e1);     // pass 1: cb1 codes
    } else {
        int m = t - 128;
        g_dec0[j * 128 + m] = dot64(c0r, w_out + m * 64) + b_out[m];
    }
    if (t == 0) {
        float n = 0.f, db = 0.f;
        for (int d = 0; d < 64; ++d) { n += c0r[d]*c0r[d]; db += b_in[d]*c0r[d]; }
        g_adj0[j] = n - 2.f * db;
    }
    if (t == 32) {
        float n = 0.f, db = 0.f;
        for (int d = 0; d < 64; ++d) { n += c1r[d]*c1r[d]; db += b_in[d]*c1r[d]; }
        g_adj1[j] = n - 2.f * db;
    }
}

__device__ __forceinline__ void mma_bf16(float* d, const uint32_t* a,
                                         uint32_t b0, uint32_t b1) {
    asm volatile(
        "mma.sync.aligned.m16n8k16.row.col.f32.bf16.bf16.f32 "
        "{%0,%1,%2,%3}, {%4,%5,%6,%7}, {%8,%9}, {%0,%1,%2,%3};\n"
        : "+f"(d[0]), "+f"(d[1]), "+f"(d[2]), "+f"(d[3])
        : "r"(a[0]), "r"(a[1]), "r"(a[2]), "r"(a[3]), "r"(b0), "r"(b1));
}
__device__ __forceinline__ void ldsm_x4(uint32_t* r, uint32_t addr) {
    asm volatile("ldmatrix.sync.aligned.m8n8.x4.shared.b16 {%0,%1,%2,%3}, [%4];"
                 : "=r"(r[0]), "=r"(r[1]), "=r"(r[2]), "=r"(r[3]) : "r"(addr));
}
__device__ __forceinline__ uint32_t smem_u32(const void* p) {
    uint32_t a;
    asm("{ .reg .u64 t; cvta.to.shared.u64 t, %1; cvt.u32.u64 %0, t; }" : "=r"(a) : "l"(p));
    return a;
}

// smem bytes:
//  A bf16 splits: 3 x [64][136] bf16 (17408 B each)   0 .. 52224
//  B12 half [8][8][32] uint4                          52224 .. 84992
//  B3  half [8][8][32] uint2                          84992 .. 101376
//  pv [64][17] f32                                    101376 .. 105728
//  pk [64][17] i32                                    105728 .. 110080
//  bv [64]  110080   bk [64] 110336   i0s 110592   i1s 110848
#define A_PAD    136
#define A_SPLIT  17408
#define OFF_B12  52224
#define OFF_B3   84992
#define OFF_PV   101376
#define OFF_PK   105728
#define OFF_BV   110080
#define OFF_BK   110336
#define OFF_I0   110592
#define OFF_I1   110848
#define SMEM_BYTES 111104

__global__ void __launch_bounds__(NTHR, 2)
rvq_main(const float* __restrict__ mel, float* __restrict__ out) {
    extern __shared__ __align__(16) uint8_t smem[];
    unsigned short* smA = (unsigned short*)smem;    // 3 x [64][136]
    uint4* smB12 = (uint4*)(smem + OFF_B12);        // [8][8][32]
    uint2* smB3  = (uint2*)(smem + OFF_B3);         // [8][8][32]
    float* pv    = (float*)(smem + OFF_PV);         // [64][17]
    int*   pk    = (int*)(smem + OFF_PK);           // [64][17]
    float* bv    = (float*)(smem + OFF_BV);
    int*   bk    = (int*)(smem + OFF_BK);
    int*   i0s   = (int*)(smem + OFF_I0);
    int*   i1s   = (int*)(smem + OFF_I1);

    const int tid  = threadIdx.x;
    const int lane = tid & 31;
    const int wid  = tid >> 5;
    const int tile = blockIdx.x;
    const int g    = lane >> 2;    // mma group id (row)
    const int tt   = lane & 3;     // thread-in-group (col pair)
    const int mw   = wid & 1;      // token half of tile
    const int nw   = wid >> 1;     // code 16-group within half
    const int tokB = mw * 32;

    // ---- stage mel -> 3 bf16 split images (once per tile) ----
    {
        const float4* mg = (const float4*)mel + (size_t)tile * 2048;
#pragma unroll
        for (int r = 0; r < 8; ++r) {
            int f = tid + NTHR * r;            // 0..2047 float4
            int tok = f >> 5, q4 = f & 31;     // col block of 4
            float4 v = mg[f];
            float e[4] = {v.x, v.y, v.z, v.w};
            unsigned short us[3][4];
#pragma unroll
            for (int q = 0; q < 4; ++q) {
                float w = e[q];
#pragma unroll
                for (int s = 0; s < 3; ++s) {
                    __nv_bfloat16 h = __float2bfloat16_rn(w);
                    us[s][q] = __bfloat16_as_ushort(h);
                    w -= __bfloat162float(h);
                }
            }
#pragma unroll
            for (int s = 0; s < 3; ++s) {
                uint2 pkd;
                pkd.x = (uint32_t)us[s][0] | ((uint32_t)us[s][1] << 16);
                pkd.y = (uint32_t)us[s][2] | ((uint32_t)us[s][3] << 16);
                *(uint2*)(smA + s * (A_SPLIT / 2) + tok * A_PAD + q4 * 4) = pkd;
            }
        }
    }

    // ldmatrix base address for this lane (row = lane&15, col-block = lane>>4)
    const uint32_t smA_u32 = smem_u32(smA);
    const uint32_t aRow = (uint32_t)(tokB + (lane & 15));
    const uint32_t aColB = (uint32_t)((lane >> 4) * 8);

#pragma unroll 1
    for (int ch = 0; ch < 2; ++ch) {
#pragma unroll 1
        for (int h = 0; h < 2; ++h) {
            __syncthreads();   // A staged / prior B+scratch reads done
            // ---- stage B half: nf in [h*8, h*8+8) ----
            {
                const uint4* gb12 = (const uint4*)g_B12;
#pragma unroll
                for (int r = 0; r < 8; ++r) {
                    int f = tid + NTHR * r;            // 0..2047
                    int kst = f >> 8, inner = f & 255;
                    smB12[f] = gb12[(ch * 8 + kst) * 512 + (h * 8) * 32 + inner];
                }
                const uint4* gb3 = (const uint4*)g_B3;
                uint4* sb3 = (uint4*)smB3;
#pragma unroll
                for (int r = 0; r < 4; ++r) {
                    int f = tid + NTHR * r;            // 0..1023
                    int kst = f >> 7, w = f & 127;
                    sb3[f] = gb3[((ch * 8 + kst) * 16 + h * 8) * 16 + w];
                }
            }
            __syncthreads();

            // ---- GEMM: warp = 32 tok x 16 codes, K=128, 6 split terms ----
            float d[2][2][4];
#pragma unroll
            for (int mf = 0; mf < 2; ++mf)
#pragma unroll
                for (int nfl = 0; nfl < 2; ++nfl)
#pragma unroll
                    for (int q = 0; q < 4; ++q) d[mf][nfl][q] = 0.f;

#pragma unroll 1
            for (int kst = 0; kst < 8; ++kst) {
                uint32_t A[2][3][4];
#pragma unroll
                for (int mf = 0; mf < 2; ++mf) {
                    uint32_t base = smA_u32
                        + ((aRow + mf * 16) * A_PAD + kst * 16 + aColB) * 2;
#pragma unroll
                    for (int s = 0; s < 3; ++s)
                        ldsm_x4(A[mf][s], base + s * A_SPLIT);
                }
#pragma unroll
                for (int nfl = 0; nfl < 2; ++nfl) {
                    const int bidx = (kst * 8 + nw * 2 + nfl) * 32 + lane;
                    uint4 b12 = smB12[bidx];
                    uint2 b3  = smB3[bidx];
#pragma unroll
                    for (int mf = 0; mf < 2; ++mf) {
                        mma_bf16(d[mf][nfl], A[mf][0], b12.x, b12.y);  // a1*b1
                        mma_bf16(d[mf][nfl], A[mf][0], b12.z, b12.w);  // a1*b2
                        mma_bf16(d[mf][nfl], A[mf][1], b12.x, b12.y);  // a2*b1
                        mma_bf16(d[mf][nfl], A[mf][1], b12.z, b12.w);  // a2*b2
                        mma_bf16(d[mf][nfl], A[mf][0], b3.x,  b3.y);   // a1*b3
                        mma_bf16(d[mf][nfl], A[mf][2], b12.x, b12.y);  // a3*b1
                    }
                }
            }

            // ---- fold adj (+Gram) and local argmin; write candidates ----
#pragma unroll
            for (int mf = 0; mf < 2; ++mf) {
#pragma unroll
                for (int rh = 0; rh < 2; ++rh) {
                    const int tok = tokB + mf * 16 + rh * 8 + g;
                    const int k0 = h * 64 + nw * 16 + tt * 2;   // nfl=0 pair
                    float s0 = d[mf][0][rh * 2], s1 = d[mf][0][rh * 2 + 1];
                    float s2 = d[mf][1][rh * 2], s3 = d[mf][1][rh * 2 + 1];
                    float v0, v1, v2, v3;
                    if (ch == 0) {
                        float2 a01 = *(const float2*)(g_adj0 + k0);
                        float2 a23 = *(const float2*)(g_adj0 + k0 + 8);
                        v0 = a01.x - 2.f * s0; v1 = a01.y - 2.f * s1;
                        v2 = a23.x - 2.f * s2; v3 = a23.y - 2.f * s3;
                    } else {
                        const float* grow = g_twoG + i0s[tok] * 128;
                        float2 a01 = *(const float2*)(g_adj1 + k0);
                        float2 a23 = *(const float2*)(g_adj1 + k0 + 8);
                        float2 g01 = *(const float2*)(grow + k0);
                        float2 g23 = *(const float2*)(grow + k0 + 8);
                        v0 = a01.x - 2.f * s0 + g01.x; v1 = a01.y - 2.f * s1 + g01.y;
                        v2 = a23.x - 2.f * s2 + g23.x; v3 = a23.y - 2.f * s3 + g23.y;
                    }
                    float best = v0; int bi = k0;
                    if (v1 < best) { best = v1; bi = k0 + 1; }
                    if (v2 < best) { best = v2; bi = k0 + 8; }
                    if (v3 < best) { best = v3; bi = k0 + 9; }
                    pv[tok * 17 + nw * 4 + tt] = best;
                    pk[tok * 17 + nw * 4 + tt] = bi;
                }
            }
            __syncthreads();

            // ---- reduce 16 slots per token, merge across halves ----
            if (tid < 64) {
                float best = pv[tid * 17]; int bi = pk[tid * 17];
#pragma unroll
                for (int l = 1; l < 16; ++l) {
                    float v = pv[tid * 17 + l]; int kk = pk[tid * 17 + l];
                    if (v < best || (v == best && kk < bi)) { best = v; bi = kk; }
                }
                if (h == 0) { bv[tid] = best; bk[tid] = bi; }
                else {
                    float b0 = bv[tid]; int kb = bk[tid];
                    if (best < b0 || (best == b0 && bi < kb)) { b0 = best; kb = bi; }
                    if (ch == 0) i0s[tid] = kb; else i1s[tid] = kb;
                }
            }
        }
    }
    __syncthreads();

    // ---- decode: out = dec0[i0] + dec1[i1] (coalesced float4) ----
    {
        const float4* d0 = (const float4*)g_dec0;
        const float4* d1 = (const float4*)g_dec1;
        float4* o4 = (float4*)out + (size_t)tile * 2048;
#pragma unroll
        for (int r = 0; r < 8; ++r) {
            int f = tid + NTHR * r;            // 0..2047
            int tok = f >> 5, m4 = f & 31;
            float4 va = d0[i0s[tok] * 32 + m4];
            float4 vb = d1[i1s[tok] * 32 + m4];
            o4[f] = make_float4(va.x + vb.x, va.y + vb.y, va.z + vb.z, va.w + vb.w);
        }
    }
}

extern "C" void kernel_launch(void* const* d_in, const int* in_sizes, int n_in,
                              void* d_out, int out_size) {
    const float* mel   = (const float*)d_in[0];
    const float* w_in  = (const float*)d_in[1];
    const float* b_in  = (const float*)d_in[2];
    const float* cb0   = (const float*)d_in[3];
    const float* cb1   = (const float*)d_in[4];
    const float* w_out = (const float*)d_in[5];
    const float* b_out = (const float*)d_in[6];
    float* out = (float*)d_out;

    cudaFuncSetAttribute(rvq_main, cudaFuncAttributeMaxDynamicSharedMemorySize, SMEM_BYTES);

    rvq_precompute<<<128, NTHR>>>(w_in, b_in, cb0, cb1, w_out, b_out);
    rvq_main<<<NTILE, NTHR, SMEM_BYTES>>>(mel, out);
}

// round 16
// speedup vs baseline: 1.7819x; 1.2922x over previous
#include <cuda_runtime.h>
#include <cuda_bf16.h>
#include <cstdint>

// RVQ via mma.sync bf16 (6-term error-free split ~ fp32 parity):
// s[tok][k] = mel @ E^T (E = [cb0;cb1] @ w_in, 256x128), argmin w/ Gram fold,
// decode via tables. A staged as 3 bf16-split images (ldmatrix); B fragment
// images read directly from L2-resident global (no smem staging).

#define NTOK   (32 * 4096)
#define TILE_T 64
#define NTILE  (NTOK / TILE_T)   // 2048
#define NTHR   256

// ---- precomputed tables ----
__device__ __align__(16) float g_twoG[128 * 128]; // 2 * cb0[j] . cb1[k]
__device__ __align__(16) float g_dec0[128 * 128]; // cb0[j] @ w_out^T + b_out
__device__ __align__(16) float g_dec1[128 * 128]; // cb1[j] @ w_out^T
__device__ __align__(16) float g_adj0[128];       // ||c0||^2 - 2 b.c0
__device__ __align__(16) float g_adj1[128];       // ||c1||^2 - 2 b.c1
// B fragment images, mma.m16n8k16 layout, 3 bf16 splits:
// idx = ((pass*8 + kst)*16 + nf)*32 + lane
// g_B12[idx] = uint4{ b0_s1, b1_s1, b0_s2, b1_s2 };  g_B3[idx] = uint2{ b0_s3, b1_s3 }
__device__ __align__(16) uint32_t g_B12[2 * 8 * 16 * 32 * 4]; // 128KB
__device__ __align__(16) uint32_t g_B3 [2 * 8 * 16 * 32 * 2]; // 64KB

__device__ __forceinline__ float dot64(const float* __restrict__ a,
                                       const float* __restrict__ b) {
    float s = 0.f;
    const float4* b4 = (const float4*)b;
#pragma unroll
    for (int q = 0; q < 16; ++q) {
        float4 v = b4[q];
        s += a[4*q+0]*v.x + a[4*q+1]*v.y + a[4*q+2]*v.z + a[4*q+3]*v.w;
    }
    return s;
}

// write one E value (3 bf16 splits) into the packed fragment images
__device__ __forceinline__ void write_B(int pass, int n, int k, float v) {
    const int nf = n >> 3, lg = n & 7;
    const int kst = k >> 4, kk = k & 15;
    const int kh = kk >> 3;          // b0 vs b1 reg
    const int lc = (kk & 7) >> 1;    // lane&3
    const int hl = kk & 1;           // lo/hi bf16 in reg
    const int lane = lg * 4 + lc;
    const int idx = ((pass * 8 + kst) * 16 + nf) * 32 + lane;
    unsigned short* B12 = (unsigned short*)g_B12;
    unsigned short* B3  = (unsigned short*)g_B3;
#pragma unroll
    for (int s = 0; s < 3; ++s) {
        __nv_bfloat16 h = __float2bfloat16_rn(v);
        unsigned short us = __bfloat16_as_ushort(h);
        if (s < 2) B12[(idx * 4 + 2 * s + kh) * 2 + hl] = us;
        else       B3 [(idx * 2 + kh) * 2 + hl] = us;
        v -= __bfloat162float(h);
    }
}

__global__ void rvq_precompute(const float* __restrict__ w_in,
                               const float* __restrict__ b_in,
                               const float* __restrict__ cb0,
                               const float* __restrict__ cb1,
                               const float* __restrict__ w_out,
                               const float* __restrict__ b_out) {
    __shared__ float c0r[64], c1r[64];
    const int j = blockIdx.x;      // 0..127
    const int t = threadIdx.x;     // 0..255
    if (t < 64)        c0r[t]      = cb0[j * 64 + t];
    else if (t < 128)  c1r[t - 64] = cb1[j * 64 + (t - 64)];
    __syncthreads();

    if (t < 128) {
        g_twoG[j * 128 + t] = 2.f * dot64(c0r, cb1 + t * 64);
        g_dec1[j * 128 + t] = dot64(c1r, w_out + t * 64);
        const int m = t;
        float e0 = 0.f, e1 = 0.f;
#pragma unroll 8
        for (int d = 0; d < 64; ++d) {
            float w = w_in[d * 128 + m];
            e0 += c0r[d] * w; e1 += c1r[d] * w;
        }
        write_B(0, j, m, e0);     // pass 0: cb0 codes
        write_B(1, j, m, e1);     // pass 1: cb1 codes
    } else {
        int m = t - 128;
        g_dec0[j * 128 + m] = dot64(c0r, w_out + m * 64) + b_out[m];
    }
    if (t == 0) {
        float n = 0.f, db = 0.f;
        for (int d = 0; d < 64; ++d) { n += c0r[d]*c0r[d]; db += b_in[d]*c0r[d]; }
        g_adj0[j] = n - 2.f * db;
    }
    if (t == 32) {
        float n = 0.f, db = 0.f;
        for (int d = 0; d < 64; ++d) { n += c1r[d]*c1r[d]; db += b_in[d]*c1r[d]; }
        g_adj1[j] = n - 2.f * db;
    }
}

__device__ __forceinline__ void mma_bf16(float* d, const uint32_t* a,
                                         uint32_t b0, uint32_t b1) {
    asm volatile(
        "mma.sync.aligned.m16n8k16.row.col.f32.bf16.bf16.f32 "
        "{%0,%1,%2,%3}, {%4,%5,%6,%7}, {%8,%9}, {%0,%1,%2,%3};\n"
        : "+f"(d[0]), "+f"(d[1]), "+f"(d[2]), "+f"(d[3])
        : "r"(a[0]), "r"(a[1]), "r"(a[2]), "r"(a[3]), "r"(b0), "r"(b1));
}
__device__ __forceinline__ void ldsm_x4(uint32_t* r, uint32_t addr) {
    asm volatile("ldmatrix.sync.aligned.m8n8.x4.shared.b16 {%0,%1,%2,%3}, [%4];"
                 : "=r"(r[0]), "=r"(r[1]), "=r"(r[2]), "=r"(r[3]) : "r"(addr));
}
__device__ __forceinline__ uint32_t smem_u32(const void* p) {
    uint32_t a;
    asm("{ .reg .u64 t; cvta.to.shared.u64 t, %1; cvt.u32.u64 %0, t; }" : "=r"(a) : "l"(p));
    return a;
}

// smem bytes:
//  A bf16 splits: 3 x [64][136] bf16 (17408 B each)   0 .. 52224
//  pv [64][17] f32    52224 .. 56576
//  pk [64][17] i32    56576 .. 60928
//  i0s 60928  i1s 61184
#define A_PAD    136
#define A_SPLIT  17408
#define OFF_PV   52224
#define OFF_PK   56576
#define OFF_I0   60928
#define OFF_I1   61184
#define SMEM_BYTES 61440

__global__ void __launch_bounds__(NTHR, 2)
rvq_main(const float* __restrict__ mel, float* __restrict__ out) {
    extern __shared__ __align__(16) uint8_t smem[];
    unsigned short* smA = (unsigned short*)smem;    // 3 x [64][136]
    float* pv  = (float*)(smem + OFF_PV);           // [64][17]
    int*   pk  = (int*)(smem + OFF_PK);             // [64][17]
    int*   i0s = (int*)(smem + OFF_I0);
    int*   i1s = (int*)(smem + OFF_I1);

    const int tid  = threadIdx.x;
    const int lane = tid & 31;
    const int wid  = tid >> 5;
    const int tile = blockIdx.x;
    const int g    = lane >> 2;    // mma group id (row)
    const int tt   = lane & 3;     // thread-in-group (col pair)
    const int mw   = wid & 1;      // token half of tile
    const int nw   = wid >> 1;     // code 32-group (4 nf)
    const int tokB = mw * 32;

    // ---- stage mel -> 3 bf16 split images (once per tile) ----
    {
        const float4* mg = (const float4*)mel + (size_t)tile * 2048;
#pragma unroll
        for (int r = 0; r < 8; ++r) {
            int f = tid + NTHR * r;            // 0..2047 float4
            int tok = f >> 5, q4 = f & 31;     // col block of 4
            float4 v = mg[f];
            float e[4] = {v.x, v.y, v.z, v.w};
            unsigned short us[3][4];
#pragma unroll
            for (int q = 0; q < 4; ++q) {
                float w = e[q];
#pragma unroll
                for (int s = 0; s < 3; ++s) {
                    __nv_bfloat16 h = __float2bfloat16_rn(w);
                    us[s][q] = __bfloat16_as_ushort(h);
                    w -= __bfloat162float(h);
                }
            }
#pragma unroll
            for (int s = 0; s < 3; ++s) {
                uint2 pkd;
                pkd.x = (uint32_t)us[s][0] | ((uint32_t)us[s][1] << 16);
                pkd.y = (uint32_t)us[s][2] | ((uint32_t)us[s][3] << 16);
                *(uint2*)(smA + s * (A_SPLIT / 2) + tok * A_PAD + q4 * 4) = pkd;
            }
        }
    }
    __syncthreads();

    // ldmatrix base address for this lane (row = lane&15, col-block = lane>>4)
    const uint32_t smA_u32 = smem_u32(smA);
    const uint32_t aRow = (uint32_t)(tokB + (lane & 15));
    const uint32_t aColB = (uint32_t)((lane >> 4) * 8);
    const uint4* __restrict__ gb12 = (const uint4*)g_B12;
    const uint2* __restrict__ gb3  = (const uint2*)g_B3;

#pragma unroll 1
    for (int ch = 0; ch < 2; ++ch) {
        // ---- GEMM: warp = 32 tok x 32 codes (4 nf), K=128, 6 split terms ----
        float d[2][4][4];
#pragma unroll
        for (int mf = 0; mf < 2; ++mf)
#pragma unroll
            for (int nfl = 0; nfl < 4; ++nfl)
#pragma unroll
                for (int q = 0; q < 4; ++q) d[mf][nfl][q] = 0.f;

#pragma unroll 1
        for (int kst = 0; kst < 8; ++kst) {
            // B fragments straight from L2-resident global (coalesced)
            uint4 b12[4]; uint2 b3[4];
#pragma unroll
            for (int nfl = 0; nfl < 4; ++nfl) {
                const int bidx = ((ch * 8 + kst) * 16 + nw * 4 + nfl) * 32 + lane;
                b12[nfl] = gb12[bidx];
                b3[nfl]  = gb3[bidx];
            }
            uint32_t A[2][3][4];
#pragma unroll
            for (int mf = 0; mf < 2; ++mf) {
                uint32_t base = smA_u32
                    + ((aRow + mf * 16) * A_PAD + kst * 16 + aColB) * 2;
#pragma unroll
                for (int s = 0; s < 3; ++s)
                    ldsm_x4(A[mf][s], base + s * A_SPLIT);
            }
#pragma unroll
            for (int nfl = 0; nfl < 4; ++nfl)
#pragma unroll
                for (int mf = 0; mf < 2; ++mf) {
                    mma_bf16(d[mf][nfl], A[mf][0], b12[nfl].x, b12[nfl].y);  // a1*b1
                    mma_bf16(d[mf][nfl], A[mf][0], b12[nfl].z, b12[nfl].w);  // a1*b2
                    mma_bf16(d[mf][nfl], A[mf][1], b12[nfl].x, b12[nfl].y);  // a2*b1
                    mma_bf16(d[mf][nfl], A[mf][1], b12[nfl].z, b12[nfl].w);  // a2*b2
                    mma_bf16(d[mf][nfl], A[mf][0], b3[nfl].x,  b3[nfl].y);   // a1*b3
                    mma_bf16(d[mf][nfl], A[mf][2], b12[nfl].x, b12[nfl].y);  // a3*b1
                }
        }

        // ---- fold adj (+Gram), thread-local argmin over 8 codes ----
#pragma unroll
        for (int mf = 0; mf < 2; ++mf) {
#pragma unroll
            for (int rh = 0; rh < 2; ++rh) {
                const int tok = tokB + mf * 16 + rh * 8 + g;
                const int kc  = nw * 32 + tt * 2;
                const float* grow = (ch == 0) ? g_adj0 : g_twoG + i0s[tok] * 128;
                float best = 3.402823466e38f; int bi = 0;
#pragma unroll
                for (int nfl = 0; nfl < 4; ++nfl) {
                    const int k = kc + nfl * 8;
                    float s0 = d[mf][nfl][rh * 2], s1 = d[mf][nfl][rh * 2 + 1];
                    float v0, v1;
                    if (ch == 0) {
                        float2 a01 = *(const float2*)(g_adj0 + k);
                        v0 = a01.x - 2.f * s0; v1 = a01.y - 2.f * s1;
                    } else {
                        float2 a01 = *(const float2*)(g_adj1 + k);
                        float2 g01 = *(const float2*)(grow + k);
                        v0 = a01.x - 2.f * s0 + g01.x; v1 = a01.y - 2.f * s1 + g01.y;
                    }
                    if (v0 < best) { best = v0; bi = k; }
                    if (v1 < best) { best = v1; bi = k + 1; }
                }
                pv[tok * 17 + nw * 4 + tt] = best;
                pk[tok * 17 + nw * 4 + tt] = bi;
            }
        }
        __syncthreads();

        // ---- reduce 16 slots per token ((v,k) lexicographic = jnp.argmin) ----
        if (tid < 64) {
            float best = pv[tid * 17]; int bi = pk[tid * 17];
#pragma unroll
            for (int l = 1; l < 16; ++l) {
                float v = pv[tid * 17 + l]; int kk = pk[tid * 17 + l];
                if (v < best || (v == best && kk < bi)) { best = v; bi = kk; }
            }
            if (ch == 0) i0s[tid] = bi; else i1s[tid] = bi;
        }
        __syncthreads();
    }

    // ---- decode: out = dec0[i0] + dec1[i1] (coalesced float4) ----
    {
        const float4* d0 = (const float4*)g_dec0;
        const float4* d1 = (const float4*)g_dec1;
        float4* o4 = (float4*)out + (size_t)tile * 2048;
#pragma unroll
        for (int r = 0; r < 8; ++r) {
            int f = tid + NTHR * r;            // 0..2047
            int tok = f >> 5, m4 = f & 31;
            float4 va = d0[i0s[tok] * 32 + m4];
            float4 vb = d1[i1s[tok] * 32 + m4];
            o4[f] = make_float4(va.x + vb.x, va.y + vb.y, va.z + vb.z, va.w + vb.w);
        }
    }
}

extern "C" void kernel_launch(void* const* d_in, const int* in_sizes, int n_in,
                              void* d_out, int out_size) {
    const float* mel   = (const float*)d_in[0];
    const float* w_in  = (const float*)d_in[1];
    const float* b_in  = (const float*)d_in[2];
    const float* cb0   = (const float*)d_in[3];
    const float* cb1   = (const float*)d_in[4];
    const float* w_out = (const float*)d_in[5];
    const float* b_out = (const float*)d_in[6];
    float* out = (float*)d_out;

    cudaFuncSetAttribute(rvq_main, cudaFuncAttributeMaxDynamicSharedMemorySize, SMEM_BYTES);

    rvq_precompute<<<128, NTHR>>>(w_in, b_in, cb0, cb1, w_out, b_out);
    rvq_main<<<NTILE, NTHR, SMEM_BYTES>>>(mel, out);
}

// round 17
// speedup vs baseline: 1.9178x; 1.0762x over previous
#include <cuda_runtime.h>
#include <cuda_bf16.h>
#include <cstdint>

// RVQ via mma.sync bf16 (6-term error-free split ~ fp32 parity):
// s[tok][k] = mel @ E^T (E = [cb0;cb1] @ w_in, 256x128), argmin w/ Gram fold,
// decode via tables. A staged as 3 bf16-split images (ldmatrix); B fragment
// images read from L2-resident global with register double-buffer prefetch.

#define NTOK   (32 * 4096)
#define TILE_T 64
#define NTILE  (NTOK / TILE_T)   // 2048
#define NTHR   256

// ---- precomputed tables ----
__device__ __align__(16) float g_twoG[128 * 128]; // 2 * cb0[j] . cb1[k]
__device__ __align__(16) float g_dec0[128 * 128]; // cb0[j] @ w_out^T + b_out
__device__ __align__(16) float g_dec1[128 * 128]; // cb1[j] @ w_out^T
__device__ __align__(16) float g_adj0[128];       // ||c0||^2 - 2 b.c0
__device__ __align__(16) float g_adj1[128];       // ||c1||^2 - 2 b.c1
// B fragment images, mma.m16n8k16 layout, 3 bf16 splits:
// idx = ((pass*8 + kst)*16 + nf)*32 + lane
// g_B12[idx] = uint4{ b0_s1, b1_s1, b0_s2, b1_s2 };  g_B3[idx] = uint2{ b0_s3, b1_s3 }
__device__ __align__(16) uint32_t g_B12[2 * 8 * 16 * 32 * 4]; // 128KB
__device__ __align__(16) uint32_t g_B3 [2 * 8 * 16 * 32 * 2]; // 64KB

__device__ __forceinline__ float dot64(const float* __restrict__ a,
                                       const float* __restrict__ b) {
    float s = 0.f;
    const float4* b4 = (const float4*)b;
#pragma unroll
    for (int q = 0; q < 16; ++q) {
        float4 v = b4[q];
        s += a[4*q+0]*v.x + a[4*q+1]*v.y + a[4*q+2]*v.z + a[4*q+3]*v.w;
    }
    return s;
}

// write one E value (3 bf16 splits) into the packed fragment images
__device__ __forceinline__ void write_B(int pass, int n, int k, float v) {
    const int nf = n >> 3, lg = n & 7;
    const int kst = k >> 4, kk = k & 15;
    const int kh = kk >> 3;          // b0 vs b1 reg
    const int lc = (kk & 7) >> 1;    // lane&3
    const int hl = kk & 1;           // lo/hi bf16 in reg
    const int lane = lg * 4 + lc;
    const int idx = ((pass * 8 + kst) * 16 + nf) * 32 + lane;
    unsigned short* B12 = (unsigned short*)g_B12;
    unsigned short* B3  = (unsigned short*)g_B3;
#pragma unroll
    for (int s = 0; s < 3; ++s) {
        __nv_bfloat16 h = __float2bfloat16_rn(v);
        unsigned short us = __bfloat16_as_ushort(h);
        if (s < 2) B12[(idx * 4 + 2 * s + kh) * 2 + hl] = us;
        else       B3 [(idx * 2 + kh) * 2 + hl] = us;
        v -= __bfloat162float(h);
    }
}

__global__ void rvq_precompute(const float* __restrict__ w_in,
                               const float* __restrict__ b_in,
                               const float* __restrict__ cb0,
                               const float* __restrict__ cb1,
                               const float* __restrict__ w_out,
                               const float* __restrict__ b_out) {
    __shared__ float c0r[64], c1r[64];
    const int j = blockIdx.x;      // 0..127
    const int t = threadIdx.x;     // 0..255
    if (t < 64)        c0r[t]      = cb0[j * 64 + t];
    else if (t < 128)  c1r[t - 64] = cb1[j * 64 + (t - 64)];
    __syncthreads();

    if (t < 128) {
        g_twoG[j * 128 + t] = 2.f * dot64(c0r, cb1 + t * 64);
        g_dec1[j * 128 + t] = dot64(c1r, w_out + t * 64);
        const int m = t;
        float e0 = 0.f, e1 = 0.f;
#pragma unroll 8
        for (int d = 0; d < 64; ++d) {
            float w = w_in[d * 128 + m];
            e0 += c0r[d] * w; e1 += c1r[d] * w;
        }
        write_B(0, j, m, e0);     // pass 0: cb0 codes
        write_B(1, j, m, e1);     // pass 1: cb1 codes
    } else {
        int m = t - 128;
        g_dec0[j * 128 + m] = dot64(c0r, w_out + m * 64) + b_out[m];
    }
    if (t == 0) {
        float n = 0.f, db = 0.f;
        for (int d = 0; d < 64; ++d) { n += c0r[d]*c0r[d]; db += b_in[d]*c0r[d]; }
        g_adj0[j] = n - 2.f * db;
    }
    if (t == 32) {
        float n = 0.f, db = 0.f;
        for (int d = 0; d < 64; ++d) { n += c1r[d]*c1r[d]; db += b_in[d]*c1r[d]; }
        g_adj1[j] = n - 2.f * db;
    }
}

__device__ __forceinline__ void mma_bf16(float* d, const uint32_t* a,
                                         uint32_t b0, uint32_t b1) {
    asm volatile(
        "mma.sync.aligned.m16n8k16.row.col.f32.bf16.bf16.f32 "
        "{%0,%1,%2,%3}, {%4,%5,%6,%7}, {%8,%9}, {%0,%1,%2,%3};\n"
        : "+f"(d[0]), "+f"(d[1]), "+f"(d[2]), "+f"(d[3])
        : "r"(a[0]), "r"(a[1]), "r"(a[2]), "r"(a[3]), "r"(b0), "r"(b1));
}
__device__ __forceinline__ void ldsm_x4(uint32_t* r, uint32_t addr) {
    asm volatile("ldmatrix.sync.aligned.m8n8.x4.shared.b16 {%0,%1,%2,%3}, [%4];"
                 : "=r"(r[0]), "=r"(r[1]), "=r"(r[2]), "=r"(r[3]) : "r"(addr));
}
__device__ __forceinline__ uint32_t smem_u32(const void* p) {
    uint32_t a;
    asm("{ .reg .u64 t; cvta.to.shared.u64 t, %1; cvt.u32.u64 %0, t; }" : "=r"(a) : "l"(p));
    return a;
}

// smem bytes:
//  A bf16 splits: 3 x [64][136] bf16 (17408 B each)   0 .. 52224
//  pv [64][17] f32    52224 .. 56576
//  pk [64][17] i32    56576 .. 60928
//  i0s 60928  i1s 61184
#define A_PAD    136
#define A_SPLIT  17408
#define OFF_PV   52224
#define OFF_PK   56576
#define OFF_I0   60928
#define OFF_I1   61184
#define SMEM_BYTES 61440

__global__ void __launch_bounds__(NTHR, 2)
rvq_main(const float* __restrict__ mel, float* __restrict__ out) {
    extern __shared__ __align__(16) uint8_t smem[];
    unsigned short* smA = (unsigned short*)smem;    // 3 x [64][136]
    float* pv  = (float*)(smem + OFF_PV);           // [64][17]
    int*   pk  = (int*)(smem + OFF_PK);             // [64][17]
    int*   i0s = (int*)(smem + OFF_I0);
    int*   i1s = (int*)(smem + OFF_I1);

    const int tid  = threadIdx.x;
    const int lane = tid & 31;
    const int wid  = tid >> 5;
    const int tile = blockIdx.x;
    const int g    = lane >> 2;    // mma group id (row)
    const int tt   = lane & 3;     // thread-in-group (col pair)
    const int mw   = wid & 1;      // token half of tile
    const int nw   = wid >> 1;     // code 32-group (4 nf)
    const int tokB = mw * 32;

    // ---- stage mel -> 3 bf16 split images (once per tile) ----
    {
        const float4* mg = (const float4*)mel + (size_t)tile * 2048;
#pragma unroll
        for (int r = 0; r < 8; ++r) {
            int f = tid + NTHR * r;            // 0..2047 float4
            int tok = f >> 5, q4 = f & 31;     // col block of 4
            float4 v = mg[f];
            float e[4] = {v.x, v.y, v.z, v.w};
            unsigned short us[3][4];
#pragma unroll
            for (int q = 0; q < 4; ++q) {
                float w = e[q];
#pragma unroll
                for (int s = 0; s < 3; ++s) {
                    __nv_bfloat16 h = __float2bfloat16_rn(w);
                    us[s][q] = __bfloat16_as_ushort(h);
                    w -= __bfloat162float(h);
                }
            }
#pragma unroll
            for (int s = 0; s < 3; ++s) {
                uint2 pkd;
                pkd.x = (uint32_t)us[s][0] | ((uint32_t)us[s][1] << 16);
                pkd.y = (uint32_t)us[s][2] | ((uint32_t)us[s][3] << 16);
                *(uint2*)(smA + s * (A_SPLIT / 2) + tok * A_PAD + q4 * 4) = pkd;
            }
        }
    }
    __syncthreads();

    // ldmatrix base address for this lane (row = lane&15, col-block = lane>>4)
    const uint32_t smA_u32 = smem_u32(smA);
    const uint32_t aRow = (uint32_t)(tokB + (lane & 15));
    const uint32_t aColB = (uint32_t)((lane >> 4) * 8);
    const uint4* __restrict__ gb12 = (const uint4*)g_B12;
    const uint2* __restrict__ gb3  = (const uint2*)g_B3;

#pragma unroll 1
    for (int ch = 0; ch < 2; ++ch) {
        // ---- GEMM: warp = 32 tok x 32 codes (4 nf), K=128, 6 split terms,
        //      register double-buffered B prefetch over kst ----
        float d[2][4][4];
#pragma unroll
        for (int mf = 0; mf < 2; ++mf)
#pragma unroll
            for (int nfl = 0; nfl < 4; ++nfl)
#pragma unroll
                for (int q = 0; q < 4; ++q) d[mf][nfl][q] = 0.f;

        uint4 b12[2][4]; uint2 b3[2][4];
        // prologue: load kst=0 into buffer 0
#pragma unroll
        for (int nfl = 0; nfl < 4; ++nfl) {
            const int bidx = ((ch * 8 + 0) * 16 + nw * 4 + nfl) * 32 + lane;
            b12[0][nfl] = gb12[bidx];
            b3[0][nfl]  = gb3[bidx];
        }

#pragma unroll
        for (int kst = 0; kst < 8; ++kst) {
            const int cur = kst & 1, nxt = cur ^ 1;
            // prefetch kst+1 (drains behind this kst's MMAs)
            if (kst < 7) {
#pragma unroll
                for (int nfl = 0; nfl < 4; ++nfl) {
                    const int bidx = ((ch * 8 + kst + 1) * 16 + nw * 4 + nfl) * 32 + lane;
                    b12[nxt][nfl] = gb12[bidx];
                    b3[nxt][nfl]  = gb3[bidx];
                }
            }
            uint32_t A[2][3][4];
#pragma unroll
            for (int mf = 0; mf < 2; ++mf) {
                uint32_t base = smA_u32
                    + ((aRow + mf * 16) * A_PAD + kst * 16 + aColB) * 2;
#pragma unroll
                for (int s = 0; s < 3; ++s)
                    ldsm_x4(A[mf][s], base + s * A_SPLIT);
            }
            // term-outer: consecutive HMMAs hit 8 independent accumulators;
            // per-accumulator order unchanged (a1b1,a1b2,a2b1,a2b2,a1b3,a3b1)
#pragma unroll
            for (int t = 0; t < 6; ++t) {
                const int sa = (t == 2 || t == 3) ? 1 : (t == 5 ? 2 : 0);
#pragma unroll
                for (int nfl = 0; nfl < 4; ++nfl) {
                    uint32_t bx, by;
                    if (t == 1 || t == 3)      { bx = b12[cur][nfl].z; by = b12[cur][nfl].w; }
                    else if (t == 4)           { bx = b3[cur][nfl].x;  by = b3[cur][nfl].y;  }
                    else                       { bx = b12[cur][nfl].x; by = b12[cur][nfl].y; }
#pragma unroll
                    for (int mf = 0; mf < 2; ++mf)
                        mma_bf16(d[mf][nfl], A[mf][sa], bx, by);
                }
            }
        }

        // ---- fold adj (+Gram), thread-local argmin over 8 codes ----
#pragma unroll
        for (int mf = 0; mf < 2; ++mf) {
#pragma unroll
            for (int rh = 0; rh < 2; ++rh) {
                const int tok = tokB + mf * 16 + rh * 8 + g;
                const int kc  = nw * 32 + tt * 2;
                const float* grow = (ch == 0) ? g_adj0 : g_twoG + i0s[tok] * 128;
                float best = 3.402823466e38f; int bi = 0;
#pragma unroll
                for (int nfl = 0; nfl < 4; ++nfl) {
                    const int k = kc + nfl * 8;
                    float s0 = d[mf][nfl][rh * 2], s1 = d[mf][nfl][rh * 2 + 1];
                    float v0, v1;
                    if (ch == 0) {
                        float2 a01 = *(const float2*)(g_adj0 + k);
                        v0 = a01.x - 2.f * s0; v1 = a01.y - 2.f * s1;
                    } else {
                        float2 a01 = *(const float2*)(g_adj1 + k);
                        float2 g01 = *(const float2*)(grow + k);
                        v0 = a01.x - 2.f * s0 + g01.x; v1 = a01.y - 2.f * s1 + g01.y;
                    }
                    if (v0 < best) { best = v0; bi = k; }
                    if (v1 < best) { best = v1; bi = k + 1; }
                }
                pv[tok * 17 + nw * 4 + tt] = best;
                pk[tok * 17 + nw * 4 + tt] = bi;
            }
        }
        __syncthreads();

        // ---- reduce 16 slots per token ((v,k) lexicographic = jnp.argmin) ----
        if (tid < 64) {
            float best = pv[tid * 17]; int bi = pk[tid * 17];
#pragma unroll
            for (int l = 1; l < 16; ++l) {
                float v = pv[tid * 17 + l]; int kk = pk[tid * 17 + l];
                if (v < best || (v == best && kk < bi)) { best = v; bi = kk; }
            }
            if (ch == 0) i0s[tid] = bi; else i1s[tid] = bi;
        }
        __syncthreads();
    }

    // ---- decode: out = dec0[i0] + dec1[i1] (coalesced float4) ----
    {
        const float4* d0 = (const float4*)g_dec0;
        const float4* d1 = (const float4*)g_dec1;
        float4* o4 = (float4*)out + (size_t)tile * 2048;
#pragma unroll
        for (int r = 0; r < 8; ++r) {
            int f = tid + NTHR * r;            // 0..2047
            int tok = f >> 5, m4 = f & 31;
            float4 va = d0[i0s[tok] * 32 + m4];
            float4 vb = d1[i1s[tok] * 32 + m4];
            o4[f] = make_float4(va.x + vb.x, va.y + vb.y, va.z + vb.z, va.w + vb.w);
        }
    }
}

extern "C" void kernel_launch(void* const* d_in, const int* in_sizes, int n_in,
                              void* d_out, int out_size) {
    const float* mel   = (const float*)d_in[0];
    const float* w_in  = (const float*)d_in[1];
    const float* b_in  = (const float*)d_in[2];
    const float* cb0   = (const float*)d_in[3];
    const float* cb1   = (const float*)d_in[4];
    const float* w_out = (const float*)d_in[5];
    const float* b_out = (const float*)d_in[6];
    float* out = (float*)d_out;

    cudaFuncSetAttribute(rvq_main, cudaFuncAttributeMaxDynamicSharedMemorySize, SMEM_BYTES);

    rvq_precompute<<<128, NTHR>>>(w_in, b_in, cb0, cb1, w_out, b_out);
    rvq_main<<<NTILE, NTHR, SMEM_BYTES>>>(mel, out);
}